// round 1
// baseline (speedup 1.0000x reference)
#include <cuda_runtime.h>
#include <math.h>

#define NB 8
#define NT 256
#define NDI 64
#define ND 128
#define NROWS (NB*NT)   // 2048
#define NOUT 672        // 96*7

// ---------------- scratch (device globals; no allocation allowed) ----------
__device__ float g_f[NROWS*ND];
__device__ float g_k[NROWS*ND];
__device__ float g_v[NROWS*ND];
__device__ float g_theta[NROWS];
__device__ float g_eta[NROWS];
__device__ float g_alpha[NROWS];
__device__ float g_qlast[NB*ND];
__device__ float g_mlast[NB*ND];

__device__ __forceinline__ float gelu_t(float x) {
    // jax.nn.gelu default: tanh approximation
    float x3 = x*x*x;
    return 0.5f*x*(1.0f + tanhf(0.79788456080286535588f*(x + 0.044715f*x3)));
}
__device__ __forceinline__ float sigmoid_f(float x) {
    return 1.0f/(1.0f + expf(-x));
}

// ---------------- generic 64x64-tile SGEMM, C = act(A*B + bias) ------------
// A: MxK row-major, B: KxN row-major. grid.z selects (B0,C0) or (B1,C1).
// 256 threads, 4x4 outputs per thread. M%64==0, N%64==0, K%16==0 assumed.
__global__ __launch_bounds__(256) void sgemm2(
    const float* __restrict__ A,
    const float* __restrict__ B0, const float* __restrict__ B1,
    const float* __restrict__ bias,
    float* __restrict__ C0, float* __restrict__ C1,
    int M, int N, int K, int act)
{
    const float* Bm = (blockIdx.z == 0) ? B0 : B1;
    float* C = (blockIdx.z == 0) ? C0 : C1;

    __shared__ float As[16][64];
    __shared__ float Bs[16][64];

    int tid = threadIdx.x;
    int bm = blockIdx.x * 64;
    int bn = blockIdx.y * 64;

    int ar = tid >> 2;             // 0..63
    int ac = (tid & 3) * 4;        // 0,4,8,12
    int br = tid >> 4;             // 0..15
    int bc = (tid & 15) * 4;       // 0..60
    int rm = (tid >> 4) * 4;       // row group
    int rn = (tid & 15) * 4;       // col group

    float acc[4][4];
#pragma unroll
    for (int i = 0; i < 4; ++i)
#pragma unroll
        for (int j = 0; j < 4; ++j) acc[i][j] = 0.0f;

    for (int k0 = 0; k0 < K; k0 += 16) {
        float4 a = *(const float4*)(A + (size_t)(bm + ar) * K + k0 + ac);
        As[ac + 0][ar] = a.x;
        As[ac + 1][ar] = a.y;
        As[ac + 2][ar] = a.z;
        As[ac + 3][ar] = a.w;
        *(float4*)(&Bs[br][bc]) =
            *(const float4*)(Bm + (size_t)(k0 + br) * N + bn + bc);
        __syncthreads();
#pragma unroll
        for (int kk = 0; kk < 16; ++kk) {
            float4 av = *(const float4*)(&As[kk][rm]);
            float4 bv = *(const float4*)(&Bs[kk][rn]);
            acc[0][0] = fmaf(av.x, bv.x, acc[0][0]);
            acc[0][1] = fmaf(av.x, bv.y, acc[0][1]);
            acc[0][2] = fmaf(av.x, bv.z, acc[0][2]);
            acc[0][3] = fmaf(av.x, bv.w, acc[0][3]);
            acc[1][0] = fmaf(av.y, bv.x, acc[1][0]);
            acc[1][1] = fmaf(av.y, bv.y, acc[1][1]);
            acc[1][2] = fmaf(av.y, bv.z, acc[1][2]);
            acc[1][3] = fmaf(av.y, bv.w, acc[1][3]);
            acc[2][0] = fmaf(av.z, bv.x, acc[2][0]);
            acc[2][1] = fmaf(av.z, bv.y, acc[2][1]);
            acc[2][2] = fmaf(av.z, bv.z, acc[2][2]);
            acc[2][3] = fmaf(av.z, bv.w, acc[2][3]);
            acc[3][0] = fmaf(av.w, bv.x, acc[3][0]);
            acc[3][1] = fmaf(av.w, bv.y, acc[3][1]);
            acc[3][2] = fmaf(av.w, bv.z, acc[3][2]);
            acc[3][3] = fmaf(av.w, bv.w, acc[3][3]);
        }
        __syncthreads();
    }

    float4 bb = make_float4(0.f, 0.f, 0.f, 0.f);
    if (bias) {
        bb.x = bias[bn + rn + 0];
        bb.y = bias[bn + rn + 1];
        bb.z = bias[bn + rn + 2];
        bb.w = bias[bn + rn + 3];
    }
#pragma unroll
    for (int i = 0; i < 4; ++i) {
        float4 o;
        o.x = acc[i][0] + bb.x;
        o.y = acc[i][1] + bb.y;
        o.z = acc[i][2] + bb.z;
        o.w = acc[i][3] + bb.w;
        if (act) {
            o.x = gelu_t(o.x); o.y = gelu_t(o.y);
            o.z = gelu_t(o.z); o.w = gelu_t(o.w);
        }
        *(float4*)(C + (size_t)(bm + rm + i) * N + bn + rn) = o;
    }
}

// ---------------- meta: theta/eta/alpha from f ------------------------------
// one warp per row; grid 256, block 256 (8 warps)
__global__ __launch_bounds__(256) void meta_kernel(
    const float* __restrict__ Wm, const float* __restrict__ bm)
{
    int warp = threadIdx.x >> 5;
    int lane = threadIdx.x & 31;
    int row = blockIdx.x * 8 + warp;

    const float4* f4 = (const float4*)g_f + (size_t)row * 32;
    float4 fv = f4[lane];
    const float* wp = Wm + lane * 12;  // Wm[(4*lane+e)*3 + c]

    float d0 = fv.x*wp[0] + fv.y*wp[3] + fv.z*wp[6] + fv.w*wp[9];
    float d1 = fv.x*wp[1] + fv.y*wp[4] + fv.z*wp[7] + fv.w*wp[10];
    float d2 = fv.x*wp[2] + fv.y*wp[5] + fv.z*wp[8] + fv.w*wp[11];
#pragma unroll
    for (int o = 16; o > 0; o >>= 1) {
        d0 += __shfl_xor_sync(0xffffffffu, d0, o);
        d1 += __shfl_xor_sync(0xffffffffu, d1, o);
        d2 += __shfl_xor_sync(0xffffffffu, d2, o);
    }
    if (lane == 0) {
        g_theta[row] = 0.01f * sigmoid_f(d0 + bm[0]);
        g_eta[row]   =         sigmoid_f(d1 + bm[1]);
        g_alpha[row] = 0.1f  * sigmoid_f(d2 + bm[2]);
    }
}

// ---------------- q only at t = T-1 -----------------------------------------
__global__ __launch_bounds__(128) void qlast_kernel(const float* __restrict__ Wq)
{
    int b = blockIdx.x;
    int j = threadIdx.x;
    __shared__ float fl[ND];
    fl[j] = g_f[(size_t)(b * NT + NT - 1) * ND + j];
    __syncthreads();
    float acc = 0.f;
#pragma unroll 8
    for (int i = 0; i < ND; ++i)
        acc = fmaf(fl[i], Wq[i * ND + j], acc);
    g_qlast[b * ND + j] = acc;
}

// ---------------- the sequential scan: 1 warp per (batch,row) ---------------
// grid 128 blocks x 256 threads = 1024 warps = 8 batches x 128 rows
__global__ __launch_bounds__(256) void scan_kernel()
{
    int warp = threadIdx.x >> 5;
    int lane = threadIdx.x & 31;
    int b = blockIdx.x >> 4;
    int i = (blockIdx.x & 15) * 8 + warp;   // row index 0..127

    const float4* kb = (const float4*)g_k + (size_t)b * NT * 32 + lane;
    const float*  vb = g_v + (size_t)b * NT * ND + i;
    const float*  thp = g_theta + b * NT;
    const float*  etp = g_eta   + b * NT;
    const float*  alp = g_alpha + b * NT;

    float m0=0.f,m1=0.f,m2=0.f,m3=0.f;
    float s0=0.f,s1=0.f,s2=0.f,s3=0.f;

    float4 kt = kb[0];
    float  vt = vb[0];
    float  th = thp[0], et = etp[0], al = alp[0];

    for (int t = 0; t < NT; ++t) {
        int tn = (t + 1 < NT) ? t + 1 : t;
        // prefetch next step's operands while this step's chain resolves
        float4 kn = kb[(size_t)tn * 32];
        float  vn = vb[(size_t)tn * ND];
        float  thn = thp[tn], etn = etp[tn], aln = alp[tn];

        float p = m0*kt.x;
        p = fmaf(m1, kt.y, p);
        p = fmaf(m2, kt.z, p);
        p = fmaf(m3, kt.w, p);
#pragma unroll
        for (int o = 16; o > 0; o >>= 1)
            p += __shfl_xor_sync(0xffffffffu, p, o);

        float err = p - vt;
        float ter = th * err;
        float om  = 1.0f - al;

        s0 = et*s0 - ter*kt.x;  m0 = fmaf(om, m0, s0);
        s1 = et*s1 - ter*kt.y;  m1 = fmaf(om, m1, s1);
        s2 = et*s2 - ter*kt.z;  m2 = fmaf(om, m2, s2);
        s3 = et*s3 - ter*kt.w;  m3 = fmaf(om, m3, s3);

        kt = kn; vt = vn; th = thn; et = etn; al = aln;
    }

    // m_last = M_{T-1} @ q_{T-1}
    float4 qt = ((const float4*)g_qlast)[b * 32 + lane];
    float p = m0*qt.x;
    p = fmaf(m1, qt.y, p);
    p = fmaf(m2, qt.z, p);
    p = fmaf(m3, qt.w, p);
#pragma unroll
    for (int o = 16; o > 0; o >>= 1)
        p += __shfl_xor_sync(0xffffffffu, p, o);
    if (lane == 0) g_mlast[b * ND + i] = p;
}

// ---------------- head: gate + fuse + layernorm + gelu + output GEMV --------
// one CTA (256 threads) per batch
__global__ __launch_bounds__(256) void head_kernel(
    const float* __restrict__ W_f, const float* __restrict__ b_f,
    const float* __restrict__ W1,  const float* __restrict__ b1,
    const float* __restrict__ g1,  const float* __restrict__ be1,
    const float* __restrict__ W2,  const float* __restrict__ b2,
    float* __restrict__ out)
{
    int b = blockIdx.x;
    int tid = threadIdx.x;

    __shared__ float z[2 * ND];
    __shared__ float fused[ND];
    __shared__ float tbuf[ND];
    __shared__ float h[ND];

    if (tid < ND)       z[tid] = g_f[(size_t)(b * NT + NT - 1) * ND + tid];
    else if (tid < 2*ND) z[tid] = g_mlast[b * ND + (tid - ND)];
    __syncthreads();

    if (tid < ND) {
        float acc = b_f[tid];
#pragma unroll 8
        for (int i = 0; i < 2 * ND; ++i)
            acc = fmaf(z[i], W_f[i * ND + tid], acc);
        float g = sigmoid_f(acc);
        fused[tid] = z[tid] * g + z[ND + tid] * (1.0f - g);
    }
    __syncthreads();

    if (tid < ND) {
        float acc = b1[tid];
#pragma unroll 8
        for (int i = 0; i < ND; ++i)
            acc = fmaf(fused[i], W1[i * ND + tid], acc);
        tbuf[tid] = acc;
    }
    __syncthreads();

    // layernorm stats (redundant per-thread over 128 smem values: tiny)
    float sum = 0.f, sq = 0.f;
#pragma unroll 8
    for (int i = 0; i < ND; ++i) { float t = tbuf[i]; sum += t; sq += t*t; }
    float mu = sum * (1.0f / ND);
    float var = sq * (1.0f / ND) - mu * mu;
    float rstd = rsqrtf(var + 1e-5f);

    if (tid < ND) {
        float ln = (tbuf[tid] - mu) * rstd * g1[tid] + be1[tid];
        h[tid] = gelu_t(ln);
    }
    __syncthreads();

    for (int o = tid; o < NOUT; o += 256) {
        float acc = b2[o];
#pragma unroll 8
        for (int i = 0; i < ND; ++i)
            acc = fmaf(h[i], W2[i * NOUT + o], acc);
        out[b * NOUT + o] = acc;
    }
}

// ---------------- launch ----------------------------------------------------
extern "C" void kernel_launch(void* const* d_in, const int* in_sizes, int n_in,
                              void* d_out, int out_size)
{
    const float* x   = (const float*)d_in[0];
    const float* W_b = (const float*)d_in[1];
    const float* b_b = (const float*)d_in[2];
    const float* Wk  = (const float*)d_in[3];
    const float* Wv  = (const float*)d_in[4];
    const float* Wq  = (const float*)d_in[5];
    const float* W_m = (const float*)d_in[6];
    const float* b_m = (const float*)d_in[7];
    const float* W_f = (const float*)d_in[8];
    const float* b_f = (const float*)d_in[9];
    const float* W1  = (const float*)d_in[10];
    const float* b1  = (const float*)d_in[11];
    const float* g1  = (const float*)d_in[12];
    const float* be1 = (const float*)d_in[13];
    const float* W2  = (const float*)d_in[14];
    const float* b2  = (const float*)d_in[15];
    float* out = (float*)d_out;

    float *pf, *pk, *pv;
    cudaGetSymbolAddress((void**)&pf, g_f);
    cudaGetSymbolAddress((void**)&pk, g_k);
    cudaGetSymbolAddress((void**)&pv, g_v);

    // f = gelu(x @ W_b + b_b)     (2048 x 128, K=64)
    sgemm2<<<dim3(32, 2, 1), 256>>>(x, W_b, W_b, b_b, pf, pf,
                                    NROWS, ND, NDI, 1);
    // theta/eta/alpha = scaled sigmoid(f @ W_m + b_m)
    meta_kernel<<<256, 256>>>(W_m, b_m);
    // k = f @ Wk, v = f @ Wv      (2048 x 128, K=128), one launch via grid.z
    sgemm2<<<dim3(32, 2, 2), 256>>>(pf, Wk, Wv, nullptr, pk, pv,
                                    NROWS, ND, ND, 0);
    // q only at the last timestep
    qlast_kernel<<<NB, 128>>>(Wq);
    // sequential recurrence, 1 warp per (batch,row), state in registers
    scan_kernel<<<128, 256>>>();
    // gate + fuse + layernorm + gelu + output projection
    head_kernel<<<NB, 256>>>(W_f, b_f, W1, b1, g1, be1, W2, b2, out);
}

// round 2
// speedup vs baseline: 1.0153x; 1.0153x over previous
#include <cuda_runtime.h>
#include <math.h>

#define NB 8
#define NT 256
#define NDI 64
#define ND 128
#define NROWS (NB*NT)   // 2048
#define NOUT 672        // 96*7

// ---------------- scratch (device globals; no allocation allowed) ----------
__device__ float g_f[NROWS*ND];
__device__ float g_k[NROWS*ND];
__device__ float g_v[NROWS*ND];
__device__ float g_theta[NROWS];
__device__ float g_eta[NROWS];
__device__ float g_alpha[NROWS];
__device__ float g_qlast[NB*ND];
__device__ float g_mlast[NB*ND];
__device__ int   g_ctr[NB];

__device__ __forceinline__ float gelu_t(float x) {
    float x3 = x*x*x;
    return 0.5f*x*(1.0f + tanhf(0.79788456080286535588f*(x + 0.044715f*x3)));
}
__device__ __forceinline__ float sigmoid_f(float x) {
    return 1.0f/(1.0f + expf(-x));
}

// =====================================================================
// Launch 1: f = gelu(x @ W_b + b_b), 64x64 tiles, grid (32,2). Also
// resets the per-batch completion counters used by the scan tail.
// =====================================================================
__global__ __launch_bounds__(256) void fgemm_kernel(
    const float* __restrict__ A,      // x: 2048 x 64
    const float* __restrict__ Bm,     // W_b: 64 x 128
    const float* __restrict__ bias)   // b_b
{
    if (blockIdx.x == 0 && blockIdx.y == 0 && threadIdx.x < NB)
        g_ctr[threadIdx.x] = 0;

    __shared__ float As[16][64];
    __shared__ float Bs[16][64];

    int tid = threadIdx.x;
    int bm = blockIdx.x * 64;
    int bn = blockIdx.y * 64;

    int ar = tid >> 2;
    int ac = (tid & 3) * 4;
    int br = tid >> 4;
    int bc = (tid & 15) * 4;
    int rm = (tid >> 4) * 4;
    int rn = (tid & 15) * 4;

    float acc[4][4];
#pragma unroll
    for (int i = 0; i < 4; ++i)
#pragma unroll
        for (int j = 0; j < 4; ++j) acc[i][j] = 0.0f;

    for (int k0 = 0; k0 < NDI; k0 += 16) {
        float4 a = *(const float4*)(A + (size_t)(bm + ar) * NDI + k0 + ac);
        As[ac + 0][ar] = a.x;
        As[ac + 1][ar] = a.y;
        As[ac + 2][ar] = a.z;
        As[ac + 3][ar] = a.w;
        *(float4*)(&Bs[br][bc]) =
            *(const float4*)(Bm + (size_t)(k0 + br) * ND + bn + bc);
        __syncthreads();
#pragma unroll
        for (int kk = 0; kk < 16; ++kk) {
            float4 av = *(const float4*)(&As[kk][rm]);
            float4 bv = *(const float4*)(&Bs[kk][rn]);
            acc[0][0] = fmaf(av.x, bv.x, acc[0][0]);
            acc[0][1] = fmaf(av.x, bv.y, acc[0][1]);
            acc[0][2] = fmaf(av.x, bv.z, acc[0][2]);
            acc[0][3] = fmaf(av.x, bv.w, acc[0][3]);
            acc[1][0] = fmaf(av.y, bv.x, acc[1][0]);
            acc[1][1] = fmaf(av.y, bv.y, acc[1][1]);
            acc[1][2] = fmaf(av.y, bv.z, acc[1][2]);
            acc[1][3] = fmaf(av.y, bv.w, acc[1][3]);
            acc[2][0] = fmaf(av.z, bv.x, acc[2][0]);
            acc[2][1] = fmaf(av.z, bv.y, acc[2][1]);
            acc[2][2] = fmaf(av.z, bv.z, acc[2][2]);
            acc[2][3] = fmaf(av.z, bv.w, acc[2][3]);
            acc[3][0] = fmaf(av.w, bv.x, acc[3][0]);
            acc[3][1] = fmaf(av.w, bv.y, acc[3][1]);
            acc[3][2] = fmaf(av.w, bv.z, acc[3][2]);
            acc[3][3] = fmaf(av.w, bv.w, acc[3][3]);
        }
        __syncthreads();
    }

    float4 bb;
    bb.x = bias[bn + rn + 0];
    bb.y = bias[bn + rn + 1];
    bb.z = bias[bn + rn + 2];
    bb.w = bias[bn + rn + 3];
#pragma unroll
    for (int i = 0; i < 4; ++i) {
        float4 o;
        o.x = gelu_t(acc[i][0] + bb.x);
        o.y = gelu_t(acc[i][1] + bb.y);
        o.z = gelu_t(acc[i][2] + bb.z);
        o.w = gelu_t(acc[i][3] + bb.w);
        *(float4*)(g_f + (size_t)(bm + rm + i) * ND + bn + rn) = o;
    }
}

// =====================================================================
// Launch 2: mega kernel. All paths depend only on g_f.
//   blocks [0,128)   : k = f@Wk, v = f@Wv   (64x64 tiles)
//   blocks [128,384) : meta (theta/eta/alpha), 8 rows per block
//   blocks [384,392) : qlast (q for the final timestep), K-split by 2
// =====================================================================
__global__ __launch_bounds__(256) void mega_kernel(
    const float* __restrict__ Wk, const float* __restrict__ Wv,
    const float* __restrict__ Wq,
    const float* __restrict__ Wm, const float* __restrict__ bm_)
{
    __shared__ float smem_u[2 * 16 * 64];   // 8KB, shared by all paths
    int idx = blockIdx.x;
    int tid = threadIdx.x;

    if (idx < 128) {
        // ---------------- k/v GEMM ----------------
        float (*As)[64] = (float(*)[64])smem_u;
        float (*Bs)[64] = (float(*)[64])(smem_u + 16 * 64);
        const float* Bm = (idx >> 6) ? Wv : Wk;
        float* C = (idx >> 6) ? g_v : g_k;
        int bm = (idx & 31) * 64;
        int bn = ((idx >> 5) & 1) * 64;

        int ar = tid >> 2;
        int ac = (tid & 3) * 4;
        int br = tid >> 4;
        int bc = (tid & 15) * 4;
        int rm = (tid >> 4) * 4;
        int rn = (tid & 15) * 4;

        float acc[4][4];
#pragma unroll
        for (int i = 0; i < 4; ++i)
#pragma unroll
            for (int j = 0; j < 4; ++j) acc[i][j] = 0.0f;

        for (int k0 = 0; k0 < ND; k0 += 16) {
            float4 a = *(const float4*)(g_f + (size_t)(bm + ar) * ND + k0 + ac);
            As[ac + 0][ar] = a.x;
            As[ac + 1][ar] = a.y;
            As[ac + 2][ar] = a.z;
            As[ac + 3][ar] = a.w;
            *(float4*)(&Bs[br][bc]) =
                *(const float4*)(Bm + (size_t)(k0 + br) * ND + bn + bc);
            __syncthreads();
#pragma unroll
            for (int kk = 0; kk < 16; ++kk) {
                float4 av = *(const float4*)(&As[kk][rm]);
                float4 bv = *(const float4*)(&Bs[kk][rn]);
                acc[0][0] = fmaf(av.x, bv.x, acc[0][0]);
                acc[0][1] = fmaf(av.x, bv.y, acc[0][1]);
                acc[0][2] = fmaf(av.x, bv.z, acc[0][2]);
                acc[0][3] = fmaf(av.x, bv.w, acc[0][3]);
                acc[1][0] = fmaf(av.y, bv.x, acc[1][0]);
                acc[1][1] = fmaf(av.y, bv.y, acc[1][1]);
                acc[1][2] = fmaf(av.y, bv.z, acc[1][2]);
                acc[1][3] = fmaf(av.y, bv.w, acc[1][3]);
                acc[2][0] = fmaf(av.z, bv.x, acc[2][0]);
                acc[2][1] = fmaf(av.z, bv.y, acc[2][1]);
                acc[2][2] = fmaf(av.z, bv.z, acc[2][2]);
                acc[2][3] = fmaf(av.z, bv.w, acc[2][3]);
                acc[3][0] = fmaf(av.w, bv.x, acc[3][0]);
                acc[3][1] = fmaf(av.w, bv.y, acc[3][1]);
                acc[3][2] = fmaf(av.w, bv.z, acc[3][2]);
                acc[3][3] = fmaf(av.w, bv.w, acc[3][3]);
            }
            __syncthreads();
        }
#pragma unroll
        for (int i = 0; i < 4; ++i) {
            float4 o;
            o.x = acc[i][0]; o.y = acc[i][1];
            o.z = acc[i][2]; o.w = acc[i][3];
            *(float4*)(C + (size_t)(bm + rm + i) * ND + bn + rn) = o;
        }
    } else if (idx < 384) {
        // ---------------- meta ----------------
        int warp = tid >> 5;
        int lane = tid & 31;
        int row = (idx - 128) * 8 + warp;

        const float4* f4 = (const float4*)g_f + (size_t)row * 32;
        float4 fv = f4[lane];
        const float* wp = Wm + lane * 12;

        float d0 = fv.x*wp[0] + fv.y*wp[3] + fv.z*wp[6] + fv.w*wp[9];
        float d1 = fv.x*wp[1] + fv.y*wp[4] + fv.z*wp[7] + fv.w*wp[10];
        float d2 = fv.x*wp[2] + fv.y*wp[5] + fv.z*wp[8] + fv.w*wp[11];
#pragma unroll
        for (int o = 16; o > 0; o >>= 1) {
            d0 += __shfl_xor_sync(0xffffffffu, d0, o);
            d1 += __shfl_xor_sync(0xffffffffu, d1, o);
            d2 += __shfl_xor_sync(0xffffffffu, d2, o);
        }
        if (lane == 0) {
            g_theta[row] = 0.01f * sigmoid_f(d0 + bm_[0]);
            g_eta[row]   =         sigmoid_f(d1 + bm_[1]);
            g_alpha[row] = 0.1f  * sigmoid_f(d2 + bm_[2]);
        }
    } else {
        // ---------------- qlast (K-split by 2) ----------------
        int b = idx - 384;
        float* fl = smem_u;           // [128]
        float* part = smem_u + 128;   // [256]
        if (tid < ND)
            fl[tid] = g_f[(size_t)(b * NT + NT - 1) * ND + tid];
        __syncthreads();
        int j = tid & 127;
        int h = tid >> 7;
        float acc = 0.f;
        int i0 = h * 64;
#pragma unroll 16
        for (int i = 0; i < 64; ++i)
            acc = fmaf(fl[i0 + i], Wq[(size_t)(i0 + i) * ND + j], acc);
        part[tid] = acc;
        __syncthreads();
        if (tid < ND)
            g_qlast[b * ND + j] = part[tid] + part[tid + 128];
    }
}

// =====================================================================
// Launch 3: scan (8 lanes per row, triple-buffered prefetch) + fused
// head on the last-arriving block of each batch.
// =====================================================================
__device__ __forceinline__ void head_body(
    int b, int tid,
    const float* __restrict__ W_f, const float* __restrict__ b_f,
    const float* __restrict__ W1,  const float* __restrict__ b1,
    const float* __restrict__ g1,  const float* __restrict__ be1,
    const float* __restrict__ W2,  const float* __restrict__ b2,
    float* __restrict__ out,
    float* z, float* fused, float* tbuf, float* h)
{
    if (tid < ND)        z[tid] = g_f[(size_t)(b * NT + NT - 1) * ND + tid];
    else if (tid < 2*ND) z[tid] = g_mlast[b * ND + (tid - ND)];
    __syncthreads();

    if (tid < ND) {
        float acc = b_f[tid];
#pragma unroll 8
        for (int i = 0; i < 2 * ND; ++i)
            acc = fmaf(z[i], W_f[(size_t)i * ND + tid], acc);
        float g = sigmoid_f(acc);
        fused[tid] = z[tid] * g + z[ND + tid] * (1.0f - g);
    }
    __syncthreads();

    if (tid < ND) {
        float acc = b1[tid];
#pragma unroll 8
        for (int i = 0; i < ND; ++i)
            acc = fmaf(fused[i], W1[(size_t)i * ND + tid], acc);
        tbuf[tid] = acc;
    }
    __syncthreads();

    float sum = 0.f, sq = 0.f;
#pragma unroll 8
    for (int i = 0; i < ND; ++i) { float t = tbuf[i]; sum += t; sq += t*t; }
    float mu = sum * (1.0f / ND);
    float var = sq * (1.0f / ND) - mu * mu;
    float rstd = rsqrtf(var + 1e-5f);

    if (tid < ND) {
        float ln = (tbuf[tid] - mu) * rstd * g1[tid] + be1[tid];
        h[tid] = gelu_t(ln);
    }
    __syncthreads();

    for (int o = tid; o < NOUT; o += 256) {
        float acc = b2[o];
#pragma unroll 8
        for (int i = 0; i < ND; ++i)
            acc = fmaf(h[i], W2[(size_t)i * NOUT + o], acc);
        out[b * NOUT + o] = acc;
    }
}

__global__ __launch_bounds__(256) void scan_head_kernel(
    const float* __restrict__ W_f, const float* __restrict__ b_f,
    const float* __restrict__ W1,  const float* __restrict__ b1,
    const float* __restrict__ g1,  const float* __restrict__ be1,
    const float* __restrict__ W2,  const float* __restrict__ b2,
    float* __restrict__ out)
{
    int tid = threadIdx.x;
    int warp = tid >> 5;
    int lane = tid & 31;
    int grp = lane >> 3;       // 4 rows per warp
    int sl  = lane & 7;        // 8 lanes per row, 16 elems each
    int b = blockIdx.x >> 2;   // 4 blocks per batch
    int i = (blockIdx.x & 3) * 32 + warp * 4 + grp;

    const float* kbase = g_k + (size_t)b * NT * ND + sl * 16;
    const float* vbase = g_v + (size_t)b * NT * ND + i;
    const float* thp = g_theta + b * NT;
    const float* etp = g_eta   + b * NT;
    const float* alp = g_alpha + b * NT;

    float4 m[4], s[4];
#pragma unroll
    for (int j = 0; j < 4; ++j) {
        m[j] = make_float4(0.f,0.f,0.f,0.f);
        s[j] = make_float4(0.f,0.f,0.f,0.f);
    }

    float4 k0[4], k1[4], k2[4];
    float v0, v1, v2, th0, th1, th2, et0, et1, et2, al0, al1, al2;

#define LOADB(K,V,TH,ET,AL,t) { \
    const float4* _p = (const float4*)(kbase + (size_t)(t) * ND); \
    K[0]=_p[0]; K[1]=_p[1]; K[2]=_p[2]; K[3]=_p[3]; \
    V = vbase[(size_t)(t) * ND]; \
    TH = thp[t]; ET = etp[t]; AL = alp[t]; }

#define STEP(K,V,TH,ET,AL) { \
    float p0 = m[0].x*K[0].x; p0=fmaf(m[0].y,K[0].y,p0); p0=fmaf(m[0].z,K[0].z,p0); p0=fmaf(m[0].w,K[0].w,p0); \
    float p1 = m[1].x*K[1].x; p1=fmaf(m[1].y,K[1].y,p1); p1=fmaf(m[1].z,K[1].z,p1); p1=fmaf(m[1].w,K[1].w,p1); \
    float p2 = m[2].x*K[2].x; p2=fmaf(m[2].y,K[2].y,p2); p2=fmaf(m[2].z,K[2].z,p2); p2=fmaf(m[2].w,K[2].w,p2); \
    float p3 = m[3].x*K[3].x; p3=fmaf(m[3].y,K[3].y,p3); p3=fmaf(m[3].z,K[3].z,p3); p3=fmaf(m[3].w,K[3].w,p3); \
    float p = (p0 + p1) + (p2 + p3); \
    p += __shfl_xor_sync(0xffffffffu, p, 1); \
    p += __shfl_xor_sync(0xffffffffu, p, 2); \
    p += __shfl_xor_sync(0xffffffffu, p, 4); \
    float err = p - V; \
    float ter = TH * err; \
    float om  = 1.0f - AL; \
    _Pragma("unroll") \
    for (int j = 0; j < 4; ++j) { \
        s[j].x = fmaf(ET, s[j].x, -(ter*K[j].x)); m[j].x = fmaf(om, m[j].x, s[j].x); \
        s[j].y = fmaf(ET, s[j].y, -(ter*K[j].y)); m[j].y = fmaf(om, m[j].y, s[j].y); \
        s[j].z = fmaf(ET, s[j].z, -(ter*K[j].z)); m[j].z = fmaf(om, m[j].z, s[j].z); \
        s[j].w = fmaf(ET, s[j].w, -(ter*K[j].w)); m[j].w = fmaf(om, m[j].w, s[j].w); \
    } }

    LOADB(k0, v0, th0, et0, al0, 0)
    LOADB(k1, v1, th1, et1, al1, 1)
    LOADB(k2, v2, th2, et2, al2, 2)

    for (int t0 = 0; t0 < NT; t0 += 3) {
        STEP(k0, v0, th0, et0, al0)
        { int tn = t0 + 3 < NT ? t0 + 3 : NT - 1; LOADB(k0, v0, th0, et0, al0, tn) }
        if (t0 + 1 < NT) {
            STEP(k1, v1, th1, et1, al1)
        }
        { int tn = t0 + 4 < NT ? t0 + 4 : NT - 1; LOADB(k1, v1, th1, et1, al1, tn) }
        if (t0 + 2 < NT) {
            STEP(k2, v2, th2, et2, al2)
        }
        { int tn = t0 + 5 < NT ? t0 + 5 : NT - 1; LOADB(k2, v2, th2, et2, al2, tn) }
    }

    // m_last = M_{T-1} @ q_{T-1}
    {
        const float4* qp = (const float4*)(g_qlast + b * ND + sl * 16);
        float4 q0 = qp[0], q1 = qp[1], q2 = qp[2], q3 = qp[3];
        float p0 = m[0].x*q0.x; p0=fmaf(m[0].y,q0.y,p0); p0=fmaf(m[0].z,q0.z,p0); p0=fmaf(m[0].w,q0.w,p0);
        float p1 = m[1].x*q1.x; p1=fmaf(m[1].y,q1.y,p1); p1=fmaf(m[1].z,q1.z,p1); p1=fmaf(m[1].w,q1.w,p1);
        float p2 = m[2].x*q2.x; p2=fmaf(m[2].y,q2.y,p2); p2=fmaf(m[2].z,q2.z,p2); p2=fmaf(m[2].w,q2.w,p2);
        float p3 = m[3].x*q3.x; p3=fmaf(m[3].y,q3.y,p3); p3=fmaf(m[3].z,q3.z,p3); p3=fmaf(m[3].w,q3.w,p3);
        float p = (p0 + p1) + (p2 + p3);
        p += __shfl_xor_sync(0xffffffffu, p, 1);
        p += __shfl_xor_sync(0xffffffffu, p, 2);
        p += __shfl_xor_sync(0xffffffffu, p, 4);
        if (sl == 0) g_mlast[b * ND + i] = p;
    }

    // -------- completion counting; last block of each batch runs the head
    __shared__ float z[2 * ND];
    __shared__ float fusedv[ND];
    __shared__ float tbuf[ND];
    __shared__ float h[ND];
    __shared__ int sflag;

    __threadfence();
    __syncthreads();
    if (tid == 0) sflag = atomicAdd(&g_ctr[b], 1);
    __syncthreads();
    if (sflag == 3) {
        __threadfence();
        head_body(b, tid, W_f, b_f, W1, b1, g1, be1, W2, b2, out,
                  z, fusedv, tbuf, h);
    }
}

// ---------------- launch ----------------------------------------------------
extern "C" void kernel_launch(void* const* d_in, const int* in_sizes, int n_in,
                              void* d_out, int out_size)
{
    const float* x   = (const float*)d_in[0];
    const float* W_b = (const float*)d_in[1];
    const float* b_b = (const float*)d_in[2];
    const float* Wk  = (const float*)d_in[3];
    const float* Wv  = (const float*)d_in[4];
    const float* Wq  = (const float*)d_in[5];
    const float* W_m = (const float*)d_in[6];
    const float* b_m = (const float*)d_in[7];
    const float* W_f = (const float*)d_in[8];
    const float* b_f = (const float*)d_in[9];
    const float* W1  = (const float*)d_in[10];
    const float* b1  = (const float*)d_in[11];
    const float* g1  = (const float*)d_in[12];
    const float* be1 = (const float*)d_in[13];
    const float* W2  = (const float*)d_in[14];
    const float* b2  = (const float*)d_in[15];
    float* out = (float*)d_out;

    // f = gelu(x @ W_b + b_b), plus counter reset
    fgemm_kernel<<<dim3(32, 2), 256>>>(x, W_b, b_b);
    // k/v GEMM + meta + qlast, all concurrent (depend only on f)
    mega_kernel<<<392, 256>>>(Wk, Wv, Wq, W_m, b_m);
    // scan + fused head tail
    scan_head_kernel<<<32, 256>>>(W_f, b_f, W1, b1, g1, be1, W2, b2, out);
}

// round 3
// speedup vs baseline: 1.0165x; 1.0012x over previous
#include <cuda_runtime.h>
#include <math.h>

#define NB 8
#define NT 256
#define NDI 64
#define ND 128
#define NROWS (NB*NT)   // 2048
#define NOUT 672        // 96*7

// ---------------- scratch (device globals; no allocation allowed) ----------
__device__ float g_f[NROWS*ND];
__device__ float g_k[NROWS*ND];
__device__ float g_v[NROWS*ND];
__device__ float g_theta[NROWS];
__device__ float g_eta[NROWS];
__device__ float g_alpha[NROWS];
__device__ float g_qlast[NB*ND];
__device__ float g_mlast[NB*ND];
__device__ int   g_ctr[NB];

__device__ __forceinline__ float gelu_t(float x) {
    float x3 = x*x*x;
    return 0.5f*x*(1.0f + tanhf(0.79788456080286535588f*(x + 0.044715f*x3)));
}
__device__ __forceinline__ float sigmoid_f(float x) {
    return 1.0f/(1.0f + expf(-x));
}

// =====================================================================
// Launch 1: f = gelu(x @ W_b + b_b), 64x64 tiles, grid (32,2). Also
// resets the per-batch completion counters used by the scan tail.
// =====================================================================
__global__ __launch_bounds__(256) void fgemm_kernel(
    const float* __restrict__ A,      // x: 2048 x 64
    const float* __restrict__ Bm,     // W_b: 64 x 128
    const float* __restrict__ bias)   // b_b
{
    if (blockIdx.x == 0 && blockIdx.y == 0 && threadIdx.x < NB)
        g_ctr[threadIdx.x] = 0;

    __shared__ float As[16][64];
    __shared__ float Bs[16][64];

    int tid = threadIdx.x;
    int bm = blockIdx.x * 64;
    int bn = blockIdx.y * 64;

    int ar = tid >> 2;
    int ac = (tid & 3) * 4;
    int br = tid >> 4;
    int bc = (tid & 15) * 4;
    int rm = (tid >> 4) * 4;
    int rn = (tid & 15) * 4;

    float acc[4][4];
#pragma unroll
    for (int i = 0; i < 4; ++i)
#pragma unroll
        for (int j = 0; j < 4; ++j) acc[i][j] = 0.0f;

    for (int k0 = 0; k0 < NDI; k0 += 16) {
        float4 a = *(const float4*)(A + (size_t)(bm + ar) * NDI + k0 + ac);
        As[ac + 0][ar] = a.x;
        As[ac + 1][ar] = a.y;
        As[ac + 2][ar] = a.z;
        As[ac + 3][ar] = a.w;
        *(float4*)(&Bs[br][bc]) =
            *(const float4*)(Bm + (size_t)(k0 + br) * ND + bn + bc);
        __syncthreads();
#pragma unroll
        for (int kk = 0; kk < 16; ++kk) {
            float4 av = *(const float4*)(&As[kk][rm]);
            float4 bv = *(const float4*)(&Bs[kk][rn]);
            acc[0][0] = fmaf(av.x, bv.x, acc[0][0]);
            acc[0][1] = fmaf(av.x, bv.y, acc[0][1]);
            acc[0][2] = fmaf(av.x, bv.z, acc[0][2]);
            acc[0][3] = fmaf(av.x, bv.w, acc[0][3]);
            acc[1][0] = fmaf(av.y, bv.x, acc[1][0]);
            acc[1][1] = fmaf(av.y, bv.y, acc[1][1]);
            acc[1][2] = fmaf(av.y, bv.z, acc[1][2]);
            acc[1][3] = fmaf(av.y, bv.w, acc[1][3]);
            acc[2][0] = fmaf(av.z, bv.x, acc[2][0]);
            acc[2][1] = fmaf(av.z, bv.y, acc[2][1]);
            acc[2][2] = fmaf(av.z, bv.z, acc[2][2]);
            acc[2][3] = fmaf(av.z, bv.w, acc[2][3]);
            acc[3][0] = fmaf(av.w, bv.x, acc[3][0]);
            acc[3][1] = fmaf(av.w, bv.y, acc[3][1]);
            acc[3][2] = fmaf(av.w, bv.z, acc[3][2]);
            acc[3][3] = fmaf(av.w, bv.w, acc[3][3]);
        }
        __syncthreads();
    }

    float4 bb;
    bb.x = bias[bn + rn + 0];
    bb.y = bias[bn + rn + 1];
    bb.z = bias[bn + rn + 2];
    bb.w = bias[bn + rn + 3];
#pragma unroll
    for (int i = 0; i < 4; ++i) {
        float4 o;
        o.x = gelu_t(acc[i][0] + bb.x);
        o.y = gelu_t(acc[i][1] + bb.y);
        o.z = gelu_t(acc[i][2] + bb.z);
        o.w = gelu_t(acc[i][3] + bb.w);
        *(float4*)(g_f + (size_t)(bm + rm + i) * ND + bn + rn) = o;
    }
}

// =====================================================================
// Launch 2: mega kernel. All paths depend only on g_f.
//   blocks [0,128)   : k = f@Wk, v = f@Wv   (64x64 tiles)
//   blocks [128,384) : meta (theta/eta/alpha), 8 rows per block
//   blocks [384,392) : qlast (q for the final timestep), K-split by 2
// =====================================================================
__global__ __launch_bounds__(256) void mega_kernel(
    const float* __restrict__ Wk, const float* __restrict__ Wv,
    const float* __restrict__ Wq,
    const float* __restrict__ Wm, const float* __restrict__ bm_)
{
    __shared__ float smem_u[2 * 16 * 64];   // 8KB, shared by all paths
    int idx = blockIdx.x;
    int tid = threadIdx.x;

    if (idx < 128) {
        // ---------------- k/v GEMM ----------------
        float (*As)[64] = (float(*)[64])smem_u;
        float (*Bs)[64] = (float(*)[64])(smem_u + 16 * 64);
        const float* Bm = (idx >> 6) ? Wv : Wk;
        float* C = (idx >> 6) ? g_v : g_k;
        int bm = (idx & 31) * 64;
        int bn = ((idx >> 5) & 1) * 64;

        int ar = tid >> 2;
        int ac = (tid & 3) * 4;
        int br = tid >> 4;
        int bc = (tid & 15) * 4;
        int rm = (tid >> 4) * 4;
        int rn = (tid & 15) * 4;

        float acc[4][4];
#pragma unroll
        for (int i = 0; i < 4; ++i)
#pragma unroll
            for (int j = 0; j < 4; ++j) acc[i][j] = 0.0f;

        for (int k0 = 0; k0 < ND; k0 += 16) {
            float4 a = *(const float4*)(g_f + (size_t)(bm + ar) * ND + k0 + ac);
            As[ac + 0][ar] = a.x;
            As[ac + 1][ar] = a.y;
            As[ac + 2][ar] = a.z;
            As[ac + 3][ar] = a.w;
            *(float4*)(&Bs[br][bc]) =
                *(const float4*)(Bm + (size_t)(k0 + br) * ND + bn + bc);
            __syncthreads();
#pragma unroll
            for (int kk = 0; kk < 16; ++kk) {
                float4 av = *(const float4*)(&As[kk][rm]);
                float4 bv = *(const float4*)(&Bs[kk][rn]);
                acc[0][0] = fmaf(av.x, bv.x, acc[0][0]);
                acc[0][1] = fmaf(av.x, bv.y, acc[0][1]);
                acc[0][2] = fmaf(av.x, bv.z, acc[0][2]);
                acc[0][3] = fmaf(av.x, bv.w, acc[0][3]);
                acc[1][0] = fmaf(av.y, bv.x, acc[1][0]);
                acc[1][1] = fmaf(av.y, bv.y, acc[1][1]);
                acc[1][2] = fmaf(av.y, bv.z, acc[1][2]);
                acc[1][3] = fmaf(av.y, bv.w, acc[1][3]);
                acc[2][0] = fmaf(av.z, bv.x, acc[2][0]);
                acc[2][1] = fmaf(av.z, bv.y, acc[2][1]);
                acc[2][2] = fmaf(av.z, bv.z, acc[2][2]);
                acc[2][3] = fmaf(av.z, bv.w, acc[2][3]);
                acc[3][0] = fmaf(av.w, bv.x, acc[3][0]);
                acc[3][1] = fmaf(av.w, bv.y, acc[3][1]);
                acc[3][2] = fmaf(av.w, bv.z, acc[3][2]);
                acc[3][3] = fmaf(av.w, bv.w, acc[3][3]);
            }
            __syncthreads();
        }
#pragma unroll
        for (int i = 0; i < 4; ++i) {
            float4 o;
            o.x = acc[i][0]; o.y = acc[i][1];
            o.z = acc[i][2]; o.w = acc[i][3];
            *(float4*)(C + (size_t)(bm + rm + i) * ND + bn + rn) = o;
        }
    } else if (idx < 384) {
        // ---------------- meta ----------------
        int warp = tid >> 5;
        int lane = tid & 31;
        int row = (idx - 128) * 8 + warp;

        const float4* f4 = (const float4*)g_f + (size_t)row * 32;
        float4 fv = f4[lane];
        const float* wp = Wm + lane * 12;

        float d0 = fv.x*wp[0] + fv.y*wp[3] + fv.z*wp[6] + fv.w*wp[9];
        float d1 = fv.x*wp[1] + fv.y*wp[4] + fv.z*wp[7] + fv.w*wp[10];
        float d2 = fv.x*wp[2] + fv.y*wp[5] + fv.z*wp[8] + fv.w*wp[11];
#pragma unroll
        for (int o = 16; o > 0; o >>= 1) {
            d0 += __shfl_xor_sync(0xffffffffu, d0, o);
            d1 += __shfl_xor_sync(0xffffffffu, d1, o);
            d2 += __shfl_xor_sync(0xffffffffu, d2, o);
        }
        if (lane == 0) {
            g_theta[row] = 0.01f * sigmoid_f(d0 + bm_[0]);
            g_eta[row]   =         sigmoid_f(d1 + bm_[1]);
            g_alpha[row] = 0.1f  * sigmoid_f(d2 + bm_[2]);
        }
    } else {
        // ---------------- qlast (K-split by 2) ----------------
        int b = idx - 384;
        float* fl = smem_u;           // [128]
        float* part = smem_u + 128;   // [256]
        if (tid < ND)
            fl[tid] = g_f[(size_t)(b * NT + NT - 1) * ND + tid];
        __syncthreads();
        int j = tid & 127;
        int h = tid >> 7;
        float acc = 0.f;
        int i0 = h * 64;
#pragma unroll 16
        for (int i = 0; i < 64; ++i)
            acc = fmaf(fl[i0 + i], Wq[(size_t)(i0 + i) * ND + j], acc);
        part[tid] = acc;
        __syncthreads();
        if (tid < ND)
            g_qlast[b * ND + j] = part[tid] + part[tid + 128];
    }
}

// =====================================================================
// Launch 3: scan (8 lanes per row, triple-buffered prefetch) + fused
// head on the last-arriving block of each batch.
// =====================================================================
__device__ __forceinline__ void head_body(
    int b, int tid,
    const float* __restrict__ W_f, const float* __restrict__ b_f,
    const float* __restrict__ W1,  const float* __restrict__ b1,
    const float* __restrict__ g1,  const float* __restrict__ be1,
    const float* __restrict__ W2,  const float* __restrict__ b2,
    float* __restrict__ out,
    float* z, float* fused, float* tbuf, float* h)
{
    if (tid < ND)        z[tid] = g_f[(size_t)(b * NT + NT - 1) * ND + tid];
    else if (tid < 2*ND) z[tid] = g_mlast[b * ND + (tid - ND)];
    __syncthreads();

    if (tid < ND) {
        float acc = b_f[tid];
#pragma unroll 8
        for (int i = 0; i < 2 * ND; ++i)
            acc = fmaf(z[i], W_f[(size_t)i * ND + tid], acc);
        float g = sigmoid_f(acc);
        fused[tid] = z[tid] * g + z[ND + tid] * (1.0f - g);
    }
    __syncthreads();

    if (tid < ND) {
        float acc = b1[tid];
#pragma unroll 8
        for (int i = 0; i < ND; ++i)
            acc = fmaf(fused[i], W1[(size_t)i * ND + tid], acc);
        tbuf[tid] = acc;
    }
    __syncthreads();

    float sum = 0.f, sq = 0.f;
#pragma unroll 8
    for (int i = 0; i < ND; ++i) { float t = tbuf[i]; sum += t; sq += t*t; }
    float mu = sum * (1.0f / ND);
    float var = sq * (1.0f / ND) - mu * mu;
    float rstd = rsqrtf(var + 1e-5f);

    if (tid < ND) {
        float ln = (tbuf[tid] - mu) * rstd * g1[tid] + be1[tid];
        h[tid] = gelu_t(ln);
    }
    __syncthreads();

    for (int o = tid; o < NOUT; o += 256) {
        float acc = b2[o];
#pragma unroll 8
        for (int i = 0; i < ND; ++i)
            acc = fmaf(h[i], W2[(size_t)i * NOUT + o], acc);
        out[b * NOUT + o] = acc;
    }
}

__global__ __launch_bounds__(256) void scan_head_kernel(
    const float* __restrict__ W_f, const float* __restrict__ b_f,
    const float* __restrict__ W1,  const float* __restrict__ b1,
    const float* __restrict__ g1,  const float* __restrict__ be1,
    const float* __restrict__ W2,  const float* __restrict__ b2,
    float* __restrict__ out)
{
    int tid = threadIdx.x;
    int warp = tid >> 5;
    int lane = tid & 31;
    int grp = lane >> 3;       // 4 rows per warp
    int sl  = lane & 7;        // 8 lanes per row, 16 elems each
    int b = blockIdx.x >> 2;   // 4 blocks per batch
    int i = (blockIdx.x & 3) * 32 + warp * 4 + grp;

    const float* kbase = g_k + (size_t)b * NT * ND + sl * 16;
    const float* vbase = g_v + (size_t)b * NT * ND + i;
    const float* thp = g_theta + b * NT;
    const float* etp = g_eta   + b * NT;
    const float* alp = g_alpha + b * NT;

    float4 m[4], s[4];
#pragma unroll
    for (int j = 0; j < 4; ++j) {
        m[j] = make_float4(0.f,0.f,0.f,0.f);
        s[j] = make_float4(0.f,0.f,0.f,0.f);
    }

    float4 k0[4], k1[4], k2[4];
    float v0, v1, v2, th0, th1, th2, et0, et1, et2, al0, al1, al2;

#define LOADB(K,V,TH,ET,AL,t) { \
    const float4* _p = (const float4*)(kbase + (size_t)(t) * ND); \
    K[0]=_p[0]; K[1]=_p[1]; K[2]=_p[2]; K[3]=_p[3]; \
    V = vbase[(size_t)(t) * ND]; \
    TH = thp[t]; ET = etp[t]; AL = alp[t]; }

#define STEP(K,V,TH,ET,AL) { \
    float p0 = m[0].x*K[0].x; p0=fmaf(m[0].y,K[0].y,p0); p0=fmaf(m[0].z,K[0].z,p0); p0=fmaf(m[0].w,K[0].w,p0); \
    float p1 = m[1].x*K[1].x; p1=fmaf(m[1].y,K[1].y,p1); p1=fmaf(m[1].z,K[1].z,p1); p1=fmaf(m[1].w,K[1].w,p1); \
    float p2 = m[2].x*K[2].x; p2=fmaf(m[2].y,K[2].y,p2); p2=fmaf(m[2].z,K[2].z,p2); p2=fmaf(m[2].w,K[2].w,p2); \
    float p3 = m[3].x*K[3].x; p3=fmaf(m[3].y,K[3].y,p3); p3=fmaf(m[3].z,K[3].z,p3); p3=fmaf(m[3].w,K[3].w,p3); \
    float p = (p0 + p1) + (p2 + p3); \
    p += __shfl_xor_sync(0xffffffffu, p, 1); \
    p += __shfl_xor_sync(0xffffffffu, p, 2); \
    p += __shfl_xor_sync(0xffffffffu, p, 4); \
    float err = p - V; \
    float ter = TH * err; \
    float om  = 1.0f - AL; \
    _Pragma("unroll") \
    for (int j = 0; j < 4; ++j) { \
        s[j].x = fmaf(ET, s[j].x, -(ter*K[j].x)); m[j].x = fmaf(om, m[j].x, s[j].x); \
        s[j].y = fmaf(ET, s[j].y, -(ter*K[j].y)); m[j].y = fmaf(om, m[j].y, s[j].y); \
        s[j].z = fmaf(ET, s[j].z, -(ter*K[j].z)); m[j].z = fmaf(om, m[j].z, s[j].z); \
        s[j].w = fmaf(ET, s[j].w, -(ter*K[j].w)); m[j].w = fmaf(om, m[j].w, s[j].w); \
    } }

    LOADB(k0, v0, th0, et0, al0, 0)
    LOADB(k1, v1, th1, et1, al1, 1)
    LOADB(k2, v2, th2, et2, al2, 2)

    for (int t0 = 0; t0 < NT; t0 += 3) {
        STEP(k0, v0, th0, et0, al0)
        { int tn = t0 + 3 < NT ? t0 + 3 : NT - 1; LOADB(k0, v0, th0, et0, al0, tn) }
        if (t0 + 1 < NT) {
            STEP(k1, v1, th1, et1, al1)
        }
        { int tn = t0 + 4 < NT ? t0 + 4 : NT - 1; LOADB(k1, v1, th1, et1, al1, tn) }
        if (t0 + 2 < NT) {
            STEP(k2, v2, th2, et2, al2)
        }
        { int tn = t0 + 5 < NT ? t0 + 5 : NT - 1; LOADB(k2, v2, th2, et2, al2, tn) }
    }

    // m_last = M_{T-1} @ q_{T-1}
    {
        const float4* qp = (const float4*)(g_qlast + b * ND + sl * 16);
        float4 q0 = qp[0], q1 = qp[1], q2 = qp[2], q3 = qp[3];
        float p0 = m[0].x*q0.x; p0=fmaf(m[0].y,q0.y,p0); p0=fmaf(m[0].z,q0.z,p0); p0=fmaf(m[0].w,q0.w,p0);
        float p1 = m[1].x*q1.x; p1=fmaf(m[1].y,q1.y,p1); p1=fmaf(m[1].z,q1.z,p1); p1=fmaf(m[1].w,q1.w,p1);
        float p2 = m[2].x*q2.x; p2=fmaf(m[2].y,q2.y,p2); p2=fmaf(m[2].z,q2.z,p2); p2=fmaf(m[2].w,q2.w,p2);
        float p3 = m[3].x*q3.x; p3=fmaf(m[3].y,q3.y,p3); p3=fmaf(m[3].z,q3.z,p3); p3=fmaf(m[3].w,q3.w,p3);
        float p = (p0 + p1) + (p2 + p3);
        p += __shfl_xor_sync(0xffffffffu, p, 1);
        p += __shfl_xor_sync(0xffffffffu, p, 2);
        p += __shfl_xor_sync(0xffffffffu, p, 4);
        if (sl == 0) g_mlast[b * ND + i] = p;
    }

    // -------- completion counting; last block of each batch runs the head
    __shared__ float z[2 * ND];
    __shared__ float fusedv[ND];
    __shared__ float tbuf[ND];
    __shared__ float h[ND];
    __shared__ int sflag;

    __threadfence();
    __syncthreads();
    if (tid == 0) sflag = atomicAdd(&g_ctr[b], 1);
    __syncthreads();
    if (sflag == 3) {
        __threadfence();
        head_body(b, tid, W_f, b_f, W1, b1, g1, be1, W2, b2, out,
                  z, fusedv, tbuf, h);
    }
}

// ---------------- launch ----------------------------------------------------
extern "C" void kernel_launch(void* const* d_in, const int* in_sizes, int n_in,
                              void* d_out, int out_size)
{
    const float* x   = (const float*)d_in[0];
    const float* W_b = (const float*)d_in[1];
    const float* b_b = (const float*)d_in[2];
    const float* Wk  = (const float*)d_in[3];
    const float* Wv  = (const float*)d_in[4];
    const float* Wq  = (const float*)d_in[5];
    const float* W_m = (const float*)d_in[6];
    const float* b_m = (const float*)d_in[7];
    const float* W_f = (const float*)d_in[8];
    const float* b_f = (const float*)d_in[9];
    const float* W1  = (const float*)d_in[10];
    const float* b1  = (const float*)d_in[11];
    const float* g1  = (const float*)d_in[12];
    const float* be1 = (const float*)d_in[13];
    const float* W2  = (const float*)d_in[14];
    const float* b2  = (const float*)d_in[15];
    float* out = (float*)d_out;

    // f = gelu(x @ W_b + b_b), plus counter reset
    fgemm_kernel<<<dim3(32, 2), 256>>>(x, W_b, b_b);
    // k/v GEMM + meta + qlast, all concurrent (depend only on f)
    mega_kernel<<<392, 256>>>(Wk, Wv, Wq, W_m, b_m);
    // scan + fused head tail
    scan_head_kernel<<<32, 256>>>(W_f, b_f, W1, b1, g1, be1, W2, b2, out);
}

// round 4
// speedup vs baseline: 1.1383x; 1.1198x over previous
#include <cuda_runtime.h>
#include <math.h>

#define NB 8
#define NT 256
#define NDI 64
#define ND 128
#define NROWS (NB*NT)
#define NOUT 672

__device__ float g_f[NROWS*ND];
__device__ float g_k[NROWS*ND];
__device__ float g_v[NROWS*ND];
__device__ float g_theta[NROWS];
__device__ float g_eta[NROWS];
__device__ float g_alpha[NROWS];
__device__ float g_qlast[NB*ND];
__device__ float g_mlast[NB*ND];
__device__ float g_G[NB*NT*NT];     // G[b][t][tau] = k_t . k_tau
__device__ float g_W[NB*NT*NT];     // W[b][t][tau]
__device__ float g_Gq[NB*NT];
__device__ float g_mcoef[NB*NT];
__device__ int   g_ctr[16];

__device__ __forceinline__ float gelu_t(float x) {
    float x3 = x*x*x;
    return 0.5f*x*(1.0f + tanhf(0.79788456080286535588f*(x + 0.044715f*x3)));
}
__device__ __forceinline__ float sigmoid_f(float x) {
    return 1.0f/(1.0f + expf(-x));
}

// =====================================================================
// Launch 1: f = gelu(x @ W_b + b_b) + counter reset
// =====================================================================
__global__ __launch_bounds__(256) void fgemm_kernel(
    const float* __restrict__ A, const float* __restrict__ Bm,
    const float* __restrict__ bias)
{
    if (blockIdx.x == 0 && blockIdx.y == 0 && threadIdx.x < 16)
        g_ctr[threadIdx.x] = 0;

    __shared__ float As[16][64];
    __shared__ float Bs[16][64];
    int tid = threadIdx.x;
    int bm = blockIdx.x * 64, bn = blockIdx.y * 64;
    int ar = tid >> 2, ac = (tid & 3) * 4;
    int br = tid >> 4, bc = (tid & 15) * 4;
    int rm = (tid >> 4) * 4, rn = (tid & 15) * 4;

    float acc[4][4];
#pragma unroll
    for (int i = 0; i < 4; ++i)
#pragma unroll
        for (int j = 0; j < 4; ++j) acc[i][j] = 0.0f;

    for (int k0 = 0; k0 < NDI; k0 += 16) {
        float4 a = *(const float4*)(A + (size_t)(bm + ar) * NDI + k0 + ac);
        As[ac+0][ar]=a.x; As[ac+1][ar]=a.y; As[ac+2][ar]=a.z; As[ac+3][ar]=a.w;
        *(float4*)(&Bs[br][bc]) =
            *(const float4*)(Bm + (size_t)(k0 + br) * ND + bn + bc);
        __syncthreads();
#pragma unroll
        for (int kk = 0; kk < 16; ++kk) {
            float4 av = *(const float4*)(&As[kk][rm]);
            float4 bv = *(const float4*)(&Bs[kk][rn]);
            acc[0][0]=fmaf(av.x,bv.x,acc[0][0]); acc[0][1]=fmaf(av.x,bv.y,acc[0][1]);
            acc[0][2]=fmaf(av.x,bv.z,acc[0][2]); acc[0][3]=fmaf(av.x,bv.w,acc[0][3]);
            acc[1][0]=fmaf(av.y,bv.x,acc[1][0]); acc[1][1]=fmaf(av.y,bv.y,acc[1][1]);
            acc[1][2]=fmaf(av.y,bv.z,acc[1][2]); acc[1][3]=fmaf(av.y,bv.w,acc[1][3]);
            acc[2][0]=fmaf(av.z,bv.x,acc[2][0]); acc[2][1]=fmaf(av.z,bv.y,acc[2][1]);
            acc[2][2]=fmaf(av.z,bv.z,acc[2][2]); acc[2][3]=fmaf(av.z,bv.w,acc[2][3]);
            acc[3][0]=fmaf(av.w,bv.x,acc[3][0]); acc[3][1]=fmaf(av.w,bv.y,acc[3][1]);
            acc[3][2]=fmaf(av.w,bv.z,acc[3][2]); acc[3][3]=fmaf(av.w,bv.w,acc[3][3]);
        }
        __syncthreads();
    }
    float4 bb;
    bb.x=bias[bn+rn+0]; bb.y=bias[bn+rn+1]; bb.z=bias[bn+rn+2]; bb.w=bias[bn+rn+3];
#pragma unroll
    for (int i = 0; i < 4; ++i) {
        float4 o;
        o.x=gelu_t(acc[i][0]+bb.x); o.y=gelu_t(acc[i][1]+bb.y);
        o.z=gelu_t(acc[i][2]+bb.z); o.w=gelu_t(acc[i][3]+bb.w);
        *(float4*)(g_f + (size_t)(bm+rm+i) * ND + bn + rn) = o;
    }
}

// =====================================================================
// Launch 2: mega — k/v GEMM [0,128) + meta [128,384) + qlast [384,392)
// =====================================================================
__global__ __launch_bounds__(256) void mega_kernel(
    const float* __restrict__ Wk, const float* __restrict__ Wv,
    const float* __restrict__ Wq,
    const float* __restrict__ Wm, const float* __restrict__ bm_)
{
    __shared__ float smem_u[2 * 16 * 64];
    int idx = blockIdx.x, tid = threadIdx.x;

    if (idx < 128) {
        float (*As)[64] = (float(*)[64])smem_u;
        float (*Bs)[64] = (float(*)[64])(smem_u + 16 * 64);
        const float* Bm = (idx >> 6) ? Wv : Wk;
        float* C = (idx >> 6) ? g_v : g_k;
        int bm = (idx & 31) * 64, bn = ((idx >> 5) & 1) * 64;
        int ar = tid >> 2, ac = (tid & 3) * 4;
        int br = tid >> 4, bc = (tid & 15) * 4;
        int rm = (tid >> 4) * 4, rn = (tid & 15) * 4;

        float acc[4][4];
#pragma unroll
        for (int i = 0; i < 4; ++i)
#pragma unroll
            for (int j = 0; j < 4; ++j) acc[i][j] = 0.0f;

        for (int k0 = 0; k0 < ND; k0 += 16) {
            float4 a = *(const float4*)(g_f + (size_t)(bm + ar) * ND + k0 + ac);
            As[ac+0][ar]=a.x; As[ac+1][ar]=a.y; As[ac+2][ar]=a.z; As[ac+3][ar]=a.w;
            *(float4*)(&Bs[br][bc]) =
                *(const float4*)(Bm + (size_t)(k0 + br) * ND + bn + bc);
            __syncthreads();
#pragma unroll
            for (int kk = 0; kk < 16; ++kk) {
                float4 av = *(const float4*)(&As[kk][rm]);
                float4 bv = *(const float4*)(&Bs[kk][rn]);
                acc[0][0]=fmaf(av.x,bv.x,acc[0][0]); acc[0][1]=fmaf(av.x,bv.y,acc[0][1]);
                acc[0][2]=fmaf(av.x,bv.z,acc[0][2]); acc[0][3]=fmaf(av.x,bv.w,acc[0][3]);
                acc[1][0]=fmaf(av.y,bv.x,acc[1][0]); acc[1][1]=fmaf(av.y,bv.y,acc[1][1]);
                acc[1][2]=fmaf(av.y,bv.z,acc[1][2]); acc[1][3]=fmaf(av.y,bv.w,acc[1][3]);
                acc[2][0]=fmaf(av.z,bv.x,acc[2][0]); acc[2][1]=fmaf(av.z,bv.y,acc[2][1]);
                acc[2][2]=fmaf(av.z,bv.z,acc[2][2]); acc[2][3]=fmaf(av.z,bv.w,acc[2][3]);
                acc[3][0]=fmaf(av.w,bv.x,acc[3][0]); acc[3][1]=fmaf(av.w,bv.y,acc[3][1]);
                acc[3][2]=fmaf(av.w,bv.z,acc[3][2]); acc[3][3]=fmaf(av.w,bv.w,acc[3][3]);
            }
            __syncthreads();
        }
#pragma unroll
        for (int i = 0; i < 4; ++i) {
            float4 o; o.x=acc[i][0]; o.y=acc[i][1]; o.z=acc[i][2]; o.w=acc[i][3];
            *(float4*)(C + (size_t)(bm+rm+i) * ND + bn + rn) = o;
        }
    } else if (idx < 384) {
        int warp = tid >> 5, lane = tid & 31;
        int row = (idx - 128) * 8 + warp;
        const float4* f4 = (const float4*)g_f + (size_t)row * 32;
        float4 fv = f4[lane];
        const float* wp = Wm + lane * 12;
        float d0 = fv.x*wp[0] + fv.y*wp[3] + fv.z*wp[6] + fv.w*wp[9];
        float d1 = fv.x*wp[1] + fv.y*wp[4] + fv.z*wp[7] + fv.w*wp[10];
        float d2 = fv.x*wp[2] + fv.y*wp[5] + fv.z*wp[8] + fv.w*wp[11];
#pragma unroll
        for (int o = 16; o > 0; o >>= 1) {
            d0 += __shfl_xor_sync(0xffffffffu, d0, o);
            d1 += __shfl_xor_sync(0xffffffffu, d1, o);
            d2 += __shfl_xor_sync(0xffffffffu, d2, o);
        }
        if (lane == 0) {
            g_theta[row] = 0.01f * sigmoid_f(d0 + bm_[0]);
            g_eta[row]   =         sigmoid_f(d1 + bm_[1]);
            g_alpha[row] = 0.1f  * sigmoid_f(d2 + bm_[2]);
        }
    } else {
        int b = idx - 384;
        float* fl = smem_u;
        float* part = smem_u + 128;
        if (tid < ND) fl[tid] = g_f[(size_t)(b * NT + NT - 1) * ND + tid];
        __syncthreads();
        int j = tid & 127, h = tid >> 7;
        float acc = 0.f;
        int i0 = h * 64;
#pragma unroll 16
        for (int i = 0; i < 64; ++i)
            acc = fmaf(fl[i0 + i], Wq[(size_t)(i0 + i) * ND + j], acc);
        part[tid] = acc;
        __syncthreads();
        if (tid < ND) g_qlast[b * ND + j] = part[tid] + part[tid + 128];
    }
}

// =====================================================================
// Launch 3: per batch — G = K K^T (16 tiles) + Gq (1 block); last CTA
// of each batch runs the serial W/h prep.
// =====================================================================
__global__ __launch_bounds__(256) void gprep_kernel()
{
    __shared__ float smem_u[2 * 16 * 64];
    __shared__ float eta_s[NT];
    __shared__ float r_s[NT];
    __shared__ float qsm[ND];
    __shared__ int sflag;

    int b = blockIdx.x / 17;
    int r = blockIdx.x % 17;
    int tid = threadIdx.x;
    const float* Kb = g_k + (size_t)b * NT * ND;
    float* Gb = g_G + (size_t)b * NT * NT;

    if (r < 16) {
        // ----- G tile: C[I+.. , J+..] = K rows I . K rows J -----
        float (*As)[64] = (float(*)[64])smem_u;
        float (*Bs)[64] = (float(*)[64])(smem_u + 16 * 64);
        int I = (r >> 2) * 64, J = (r & 3) * 64;
        int ar = tid >> 2, ac = (tid & 3) * 4;
        int rm = (tid >> 4) * 4, rn = (tid & 15) * 4;

        float acc[4][4];
#pragma unroll
        for (int i = 0; i < 4; ++i)
#pragma unroll
            for (int j = 0; j < 4; ++j) acc[i][j] = 0.0f;

        for (int k0 = 0; k0 < ND; k0 += 16) {
            float4 a = *(const float4*)(Kb + (size_t)(I + ar) * ND + k0 + ac);
            As[ac+0][ar]=a.x; As[ac+1][ar]=a.y; As[ac+2][ar]=a.z; As[ac+3][ar]=a.w;
            float4 bvec = *(const float4*)(Kb + (size_t)(J + ar) * ND + k0 + ac);
            Bs[ac+0][ar]=bvec.x; Bs[ac+1][ar]=bvec.y; Bs[ac+2][ar]=bvec.z; Bs[ac+3][ar]=bvec.w;
            __syncthreads();
#pragma unroll
            for (int kk = 0; kk < 16; ++kk) {
                float4 av = *(const float4*)(&As[kk][rm]);
                float4 bv = *(const float4*)(&Bs[kk][rn]);
                acc[0][0]=fmaf(av.x,bv.x,acc[0][0]); acc[0][1]=fmaf(av.x,bv.y,acc[0][1]);
                acc[0][2]=fmaf(av.x,bv.z,acc[0][2]); acc[0][3]=fmaf(av.x,bv.w,acc[0][3]);
                acc[1][0]=fmaf(av.y,bv.x,acc[1][0]); acc[1][1]=fmaf(av.y,bv.y,acc[1][1]);
                acc[1][2]=fmaf(av.y,bv.z,acc[1][2]); acc[1][3]=fmaf(av.y,bv.w,acc[1][3]);
                acc[2][0]=fmaf(av.z,bv.x,acc[2][0]); acc[2][1]=fmaf(av.z,bv.y,acc[2][1]);
                acc[2][2]=fmaf(av.z,bv.z,acc[2][2]); acc[2][3]=fmaf(av.z,bv.w,acc[2][3]);
                acc[3][0]=fmaf(av.w,bv.x,acc[3][0]); acc[3][1]=fmaf(av.w,bv.y,acc[3][1]);
                acc[3][2]=fmaf(av.w,bv.z,acc[3][2]); acc[3][3]=fmaf(av.w,bv.w,acc[3][3]);
            }
            __syncthreads();
        }
#pragma unroll
        for (int i = 0; i < 4; ++i) {
            float4 o; o.x=acc[i][0]; o.y=acc[i][1]; o.z=acc[i][2]; o.w=acc[i][3];
            *(float4*)(Gb + (size_t)(I+rm+i) * NT + J + rn) = o;
        }
    } else {
        // ----- Gq[t] = k_t . q -----
        if (tid < ND) qsm[tid] = g_qlast[b * ND + tid];
        __syncthreads();
        const float* krow = Kb + (size_t)tid * ND;
        float acc = 0.f;
#pragma unroll 8
        for (int d = 0; d < ND; ++d) acc = fmaf(krow[d], qsm[d], acc);
        g_Gq[b * NT + tid] = acc;
    }

    // ----- gate; last CTA of batch does the W/h prep -----
    __threadfence();
    __syncthreads();
    if (tid == 0) sflag = atomicAdd(&g_ctr[8 + b], 1);
    __syncthreads();
    if (sflag != 16) return;
    __threadfence();

    int tau = tid;
    eta_s[tid] = g_eta[b * NT + tid];
    r_s[tid]   = 1.0f - g_alpha[b * NT + tid];
    float th   = g_theta[b * NT + tau];
    __syncthreads();

    float* Wb = g_W + (size_t)b * NT * NT;
    float h = 1.f, pp = 1.f;
    float gcur = Gb[NT + tau];
    for (int t = 1; t < NT; ++t) {
        float gnext = (t < NT-1) ? Gb[(size_t)(t+1) * NT + tau] : 0.f;
        if (tau < t) {
            Wb[(size_t)t * NT + tau] = -th * gcur * h;
            pp *= eta_s[t];
            h = fmaf(r_s[t], h, pp);
        }
        gcur = gnext;
    }
    g_mcoef[b * NT + tau] = -th * h * g_Gq[b * NT + tau];
}

// =====================================================================
// Launch 4: triangular solve (err system) + m_last + fused head.
// CTA = 256 thr = 16 rows x 16 lanes; grid = 8 batches x 8 row-groups.
// =====================================================================
template<int P>
__device__ __forceinline__ void solve_phase(
    float* rhs, float& macc, const float* __restrict__ panel,
    const float* __restrict__ mco, int u, int src_base)
{
#pragma unroll
    for (int tt = 0; tt < 16; ++tt) {
        float E = __shfl_sync(0xffffffffu, rhs[0], src_base | tt);
        if (u > tt)
            rhs[0] = fmaf(panel[(u + 16*P)*17 + tt], E, rhs[0]);
#pragma unroll
        for (int jj = 1; jj <= 15 - P; ++jj)
            rhs[jj] = fmaf(panel[(u + 16*(jj+P))*17 + tt], E, rhs[jj]);
        macc = fmaf(mco[16*P + tt], E, macc);
    }
#pragma unroll
    for (int jj = 0; jj < 15; ++jj) rhs[jj] = rhs[jj+1];
}

__device__ __forceinline__ void head_body(
    int b, int tid,
    const float* __restrict__ W_f, const float* __restrict__ b_f,
    const float* __restrict__ W1,  const float* __restrict__ b1,
    const float* __restrict__ g1,  const float* __restrict__ be1,
    const float* __restrict__ W2,  const float* __restrict__ b2,
    float* __restrict__ out,
    float* z, float* fused, float* tbuf, float* h)
{
    if (tid < ND)        z[tid] = g_f[(size_t)(b * NT + NT - 1) * ND + tid];
    else if (tid < 2*ND) z[tid] = g_mlast[b * ND + (tid - ND)];
    __syncthreads();
    if (tid < ND) {
        float acc = b_f[tid];
#pragma unroll 8
        for (int i = 0; i < 2 * ND; ++i)
            acc = fmaf(z[i], W_f[(size_t)i * ND + tid], acc);
        float g = sigmoid_f(acc);
        fused[tid] = z[tid] * g + z[ND + tid] * (1.0f - g);
    }
    __syncthreads();
    if (tid < ND) {
        float acc = b1[tid];
#pragma unroll 8
        for (int i = 0; i < ND; ++i)
            acc = fmaf(fused[i], W1[(size_t)i * ND + tid], acc);
        tbuf[tid] = acc;
    }
    __syncthreads();
    float sum = 0.f, sq = 0.f;
#pragma unroll 8
    for (int i = 0; i < ND; ++i) { float t = tbuf[i]; sum += t; sq += t*t; }
    float mu = sum * (1.0f / ND);
    float var = sq * (1.0f / ND) - mu * mu;
    float rstd = rsqrtf(var + 1e-5f);
    if (tid < ND) {
        float ln = (tbuf[tid] - mu) * rstd * g1[tid] + be1[tid];
        h[tid] = gelu_t(ln);
    }
    __syncthreads();
    for (int o = tid; o < NOUT; o += 256) {
        float acc = b2[o];
#pragma unroll 8
        for (int i = 0; i < ND; ++i)
            acc = fmaf(h[i], W2[(size_t)i * NOUT + o], acc);
        out[b * NOUT + o] = acc;
    }
}

__global__ __launch_bounds__(256) void solve_head_kernel(
    const float* __restrict__ W_f, const float* __restrict__ b_f,
    const float* __restrict__ W1,  const float* __restrict__ b1,
    const float* __restrict__ g1,  const float* __restrict__ be1,
    const float* __restrict__ W2,  const float* __restrict__ b2,
    float* __restrict__ out)
{
    __shared__ float panel[NT * 17];
    __shared__ float mco[NT];
    __shared__ float z[2 * ND];
    __shared__ float fusedv[ND];
    __shared__ float tbuf[ND];
    __shared__ float hh[ND];
    __shared__ int sflag;

    int tid = threadIdx.x;
    int b = blockIdx.x >> 3;
    int g = blockIdx.x & 7;
    int warp = tid >> 5, lane = tid & 31;
    int u = lane & 15;
    int src_base = lane & 16;
    int i = g * 16 + warp * 2 + (lane >> 4);   // row within batch

    mco[tid] = g_mcoef[b * NT + tid];

    float rhs[16];
#pragma unroll
    for (int m = 0; m < 16; ++m)
        rhs[m] = -g_v[(size_t)(b * NT + u + 16*m) * ND + i];

    const float* wrow = g_W + (size_t)b * NT * NT + (size_t)tid * NT;
    float4 pf[4];
#pragma unroll
    for (int q = 0; q < 4; ++q)
        pf[q] = *(const float4*)(wrow + 4*q);

    float macc = 0.f;

#define PH(P) { \
    __syncthreads(); \
    panel[tid*17+ 0]=pf[0].x; panel[tid*17+ 1]=pf[0].y; panel[tid*17+ 2]=pf[0].z; panel[tid*17+ 3]=pf[0].w; \
    panel[tid*17+ 4]=pf[1].x; panel[tid*17+ 5]=pf[1].y; panel[tid*17+ 6]=pf[1].z; panel[tid*17+ 7]=pf[1].w; \
    panel[tid*17+ 8]=pf[2].x; panel[tid*17+ 9]=pf[2].y; panel[tid*17+10]=pf[2].z; panel[tid*17+11]=pf[2].w; \
    panel[tid*17+12]=pf[3].x; panel[tid*17+13]=pf[3].y; panel[tid*17+14]=pf[3].z; panel[tid*17+15]=pf[3].w; \
    __syncthreads(); \
    if ((P) < 15) { \
        pf[0] = *(const float4*)(wrow + 16*((P)+1) +  0); \
        pf[1] = *(const float4*)(wrow + 16*((P)+1) +  4); \
        pf[2] = *(const float4*)(wrow + 16*((P)+1) +  8); \
        pf[3] = *(const float4*)(wrow + 16*((P)+1) + 12); \
    } \
    solve_phase<P>(rhs, macc, panel, mco, u, src_base); }

    PH(0) PH(1) PH(2) PH(3) PH(4) PH(5) PH(6) PH(7)
    PH(8) PH(9) PH(10) PH(11) PH(12) PH(13) PH(14) PH(15)
#undef PH

    if (u == 0) g_mlast[b * ND + i] = macc;

    __threadfence();
    __syncthreads();
    if (tid == 0) sflag = atomicAdd(&g_ctr[b], 1);
    __syncthreads();
    if (sflag == 7) {
        __threadfence();
        head_body(b, tid, W_f, b_f, W1, b1, g1, be1, W2, b2, out,
                  z, fusedv, tbuf, hh);
    }
}

// ---------------- launch ----------------------------------------------------
extern "C" void kernel_launch(void* const* d_in, const int* in_sizes, int n_in,
                              void* d_out, int out_size)
{
    const float* x   = (const float*)d_in[0];
    const float* W_b = (const float*)d_in[1];
    const float* b_b = (const float*)d_in[2];
    const float* Wk  = (const float*)d_in[3];
    const float* Wv  = (const float*)d_in[4];
    const float* Wq  = (const float*)d_in[5];
    const float* W_m = (const float*)d_in[6];
    const float* b_m = (const float*)d_in[7];
    const float* W_f = (const float*)d_in[8];
    const float* b_f = (const float*)d_in[9];
    const float* W1  = (const float*)d_in[10];
    const float* b1  = (const float*)d_in[11];
    const float* g1  = (const float*)d_in[12];
    const float* be1 = (const float*)d_in[13];
    const float* W2  = (const float*)d_in[14];
    const float* b2  = (const float*)d_in[15];
    float* out = (float*)d_out;

    fgemm_kernel<<<dim3(32, 2), 256>>>(x, W_b, b_b);
    mega_kernel<<<392, 256>>>(Wk, Wv, Wq, W_m, b_m);
    gprep_kernel<<<NB * 17, 256>>>();
    solve_head_kernel<<<64, 256>>>(W_f, b_f, W1, b1, g1, be1, W2, b2, out);
}